// round 3
// baseline (speedup 1.0000x reference)
#include <cuda_runtime.h>
#include <cuda_bf16.h>
#include <math.h>

// Problem constants
#define BB   4
#define LL   2048
#define LF   1025          // rfft output bins
#define PP   512
#define CC   8
#define PCN  4096          // P*C
#define NBL  8
#define BSZ  64
#define KPAD 1032          // padded line stride in complex elements
#define PSTR 66            // padded plane row stride (floats) in k_mlp

typedef unsigned long long u64;

// 135 MB frequency-domain scratch: [b][pc][k] complex, line stride KPAD
__device__ float2 g_Y[(size_t)BB * PCN * KPAD];

// single extern shared symbol, cast per-kernel
extern __shared__ unsigned char smbase[];

// ---------- small helpers ----------
__device__ __forceinline__ u64 pack2(float a, float b) {
    u64 r; asm("mov.b64 %0, {%1, %2};" : "=l"(r) : "f"(a), "f"(b)); return r;
}
__device__ __forceinline__ float2 unpack2(u64 v) {
    float2 r; asm("mov.b64 {%0, %1}, %2;" : "=f"(r.x), "=f"(r.y) : "l"(v)); return r;
}
__device__ __forceinline__ void ffma2(u64& acc, u64 a, u64 b) {
    asm("fma.rn.f32x2 %0, %1, %2, %0;" : "+l"(acc) : "l"(a), "l"(b));
}
__device__ __forceinline__ float gelu_exact(float v) {
    return 0.5f * v * (1.0f + erff(v * 0.7071067811865475f));
}

// In-smem 1024-point complex FFT (radix-2 DIT, bit-reversal first).
__device__ __forceinline__ void fft1024(float2* ls, const float2* W, int t, bool inv) {
    for (int j = t; j < 1024; j += 16) {
        int r = __brev((unsigned)j) >> 22;
        if (r > j) { float2 a = ls[j]; ls[j] = ls[r]; ls[r] = a; }
    }
    __syncthreads();
    for (int s = 0; s < 10; ++s) {
        int half = 1 << s;
        for (int m = t; m < 512; m += 16) {
            int pos = m & (half - 1);
            int i0 = ((m >> s) << (s + 1)) + pos;
            int i1 = i0 + half;
            float2 w = W[pos << (9 - s)];
            if (inv) w.y = -w.y;
            float2 a = ls[i0], bv = ls[i1];
            float tr = bv.x * w.x - bv.y * w.y;
            float ti = bv.x * w.y + bv.y * w.x;
            ls[i0] = make_float2(a.x + tr, a.y + ti);
            ls[i1] = make_float2(a.x - tr, a.y - ti);
        }
        __syncthreads();
    }
}

// ---------- K1: forward rfft (fused transpose) ----------
__global__ __launch_bounds__(256, 1) void k_fwd(const float* __restrict__ x) {
    float2* sm = (float2*)smbase;
    float2* W = sm;
    float2* lines = sm + 512;
    const int tid = threadIdx.x;
    const int u = tid >> 4, t = tid & 15;
    const int pc0 = blockIdx.x * 16;
    const int b = blockIdx.y;

    for (int j = tid; j < 512; j += 256) {
        float sv, cv; sincospif((float)j * (1.0f / 512.0f), &sv, &cv);
        W[j] = make_float2(cv, -sv);
    }
    {   // Coalesced load of 16 lines (float4 across pc)
        float* sf = (float*)lines;                     // line u at float offset u*2050
        const float* xb = x + (size_t)b * LL * PCN + pc0;
        for (int idx = tid; idx < 16 * 512; idx += 256) {
            int l = idx >> 2, q = idx & 3;
            float4 v = *(const float4*)(xb + (size_t)l * PCN + q * 4);
            int ub = q * 4;
            sf[(ub + 0) * 2050 + l] = v.x;
            sf[(ub + 1) * 2050 + l] = v.y;
            sf[(ub + 2) * 2050 + l] = v.z;
            sf[(ub + 3) * 2050 + l] = v.w;
        }
    }
    __syncthreads();

    float2* ls = lines + u * 1025;   // 1024 complex = 2048 reals (even/odd packed)
    fft1024(ls, W, t, false);

    {   // rfft unpack + ortho scale, store (k-contiguous, coalesced)
        float2* out = g_Y + ((size_t)(b * PCN + pc0 + u)) * KPAD;
        const float SC = 0.02209708691207961f;  // 1/sqrt(2048)
        for (int k = t; k <= 1024; k += 16) {
            float2 Zk = ls[k & 1023];
            float2 Zm = ls[(1024 - k) & 1023];
            float er = 0.5f * (Zk.x + Zm.x), ei = 0.5f * (Zk.y - Zm.y);
            float orr = 0.5f * (Zk.y + Zm.y), oi = 0.5f * (Zm.x - Zk.x);
            float sv, cv; sincospif((float)k * (1.0f / 1024.0f), &sv, &cv);
            float xr = er + cv * orr + sv * oi;
            float xi = ei + cv * oi - sv * orr;
            out[k] = make_float2(SC * xr, SC * xi);
        }
    }
}

// ---------- K2: block-diagonal complex MLP, in-place on g_Y ----------
// grid (17 ktiles of 64, 64 = n*8+c, B), 256 threads, occ 2.
// Thread (o, kg): output column o, 16 k's. f32x2 packs over k-pairs.
__global__ __launch_bounds__(256, 2) void k_mlp(const float* __restrict__ w1g,
                                                const float* __restrict__ b1g,
                                                const float* __restrict__ w2g,
                                                const float* __restrict__ b2g) {
    float* sm = (float*)smbase;
    unsigned* Wp1 = (unsigned*)sm;            // 4096: (bf16 w1_0, bf16 w1_1) per (i,o)
    unsigned* Wp2 = Wp1 + 4096;               // 4096
    float* Xr = (float*)(Wp2 + 4096);         // [64][PSTR]
    float* Xi = Xr + 64 * PSTR;
    float* Hr = Xi + 64 * PSTR;
    float* Hi = Hr + 64 * PSTR;
    float* B1r = Hi + 64 * PSTR;
    float* B1i = B1r + 64;
    float* B2r = B1i + 64;
    float* B2i = B2r + 64;

    const int tid = threadIdx.x;
    const int k0 = blockIdx.x * 64;
    const int n = blockIdx.y >> 3, c = blockIdx.y & 7;
    const int b = blockIdx.z;

    for (int idx = tid; idx < 4096; idx += 256) {
        __nv_bfloat162 h1 = __floats2bfloat162_rn(w1g[n * 4096 + idx],
                                                  w1g[32768 + n * 4096 + idx]);
        Wp1[idx] = *(unsigned*)&h1;
        __nv_bfloat162 h2 = __floats2bfloat162_rn(w2g[n * 4096 + idx],
                                                  w2g[32768 + n * 4096 + idx]);
        Wp2[idx] = *(unsigned*)&h2;
    }
    if (tid < 64) {
        B1r[tid] = b1g[n * 64 + tid];  B1i[tid] = b1g[512 + n * 64 + tid];
        B2r[tid] = b2g[n * 64 + tid];  B2i[tid] = b2g[512 + n * 64 + tid];
    }
    const size_t base = ((size_t)b * PCN + (size_t)n * BSZ * CC + c) * KPAD;
    for (int idx = tid; idx < 4096; idx += 256) {
        int i = idx >> 6, kk = idx & 63;
        float2 v = make_float2(0.f, 0.f);
        if (k0 + kk <= 1024) v = g_Y[base + (size_t)i * CC * KPAD + k0 + kk];
        Xr[i * PSTR + kk] = v.x;
        Xi[i * PSTR + kk] = v.y;
    }
    __syncthreads();

    const int o = tid & 63, kg = tid >> 6;
    const int ks = kg * 16;
    u64 ar[8], ai[8];

    // ---- layer 1: acc_r = b1r + X_r W0 - X_i W1 ; acc_i = b1i + X_i W0 + X_r W1
    {
        float brv = B1r[o], biv = B1i[o];
        u64 br = pack2(brv, brv), bi = pack2(biv, biv);
        #pragma unroll
        for (int p = 0; p < 8; ++p) { ar[p] = br; ai[p] = bi; }
    }
    for (int i = 0; i < 64; ++i) {
        unsigned wp = Wp1[i * 64 + o];
        float2 wf = __bfloat1622float2(*(__nv_bfloat162*)&wp);  // (w0, w1)
        u64 p0 = pack2(wf.x, wf.x);
        u64 p1 = pack2(wf.y, wf.y);
        u64 n1 = pack2(-wf.y, -wf.y);
        const float* xr = Xr + i * PSTR + ks;
        const float* xi = Xi + i * PSTR + ks;
        #pragma unroll
        for (int p = 0; p < 8; ++p) {
            u64 x2r = *(const u64*)(xr + 2 * p);   // broadcast LDS.64
            u64 x2i = *(const u64*)(xi + 2 * p);
            ffma2(ar[p], x2r, p0);
            ffma2(ar[p], x2i, n1);
            ffma2(ai[p], x2i, p0);
            ffma2(ai[p], x2r, p1);
        }
    }
    // gelu -> H planes
    #pragma unroll
    for (int p = 0; p < 8; ++p) {
        float2 vr = unpack2(ar[p]);
        float2 vi = unpack2(ai[p]);
        vr.x = gelu_exact(vr.x); vr.y = gelu_exact(vr.y);
        vi.x = gelu_exact(vi.x); vi.y = gelu_exact(vi.y);
        *(u64*)(Hr + o * PSTR + ks + 2 * p) = pack2(vr.x, vr.y);
        *(u64*)(Hi + o * PSTR + ks + 2 * p) = pack2(vi.x, vi.y);
    }
    __syncthreads();

    // ---- layer 2
    {
        float brv = B2r[o], biv = B2i[o];
        u64 br = pack2(brv, brv), bi = pack2(biv, biv);
        #pragma unroll
        for (int p = 0; p < 8; ++p) { ar[p] = br; ai[p] = bi; }
    }
    for (int i = 0; i < 64; ++i) {
        unsigned wp = Wp2[i * 64 + o];
        float2 wf = __bfloat1622float2(*(__nv_bfloat162*)&wp);
        u64 p0 = pack2(wf.x, wf.x);
        u64 p1 = pack2(wf.y, wf.y);
        u64 n1 = pack2(-wf.y, -wf.y);
        const float* hr = Hr + i * PSTR + ks;
        const float* hi = Hi + i * PSTR + ks;
        #pragma unroll
        for (int p = 0; p < 8; ++p) {
            u64 h2r = *(const u64*)(hr + 2 * p);
            u64 h2i = *(const u64*)(hi + 2 * p);
            ffma2(ar[p], h2r, p0);
            ffma2(ar[p], h2i, n1);
            ffma2(ai[p], h2i, p0);
            ffma2(ai[p], h2r, p1);
        }
    }
    // store outputs into X planes (dead after layer 1)
    #pragma unroll
    for (int p = 0; p < 8; ++p) {
        *(u64*)(Xr + o * PSTR + ks + 2 * p) = ar[p];
        *(u64*)(Xi + o * PSTR + ks + 2 * p) = ai[p];
    }
    __syncthreads();
    for (int idx = tid; idx < 4096; idx += 256) {
        int i = idx >> 6, kk = idx & 63;
        if (k0 + kk <= 1024)
            g_Y[base + (size_t)i * CC * KPAD + k0 + kk] =
                make_float2(Xr[i * PSTR + kk], Xi[i * PSTR + kk]);
    }
}

// ---------- K3: inverse rfft + residual (fused transpose back) ----------
__global__ __launch_bounds__(256, 1) void k_inv(const float* __restrict__ x,
                                                float* __restrict__ out) {
    float2* sm = (float2*)smbase;
    float2* W = sm;
    float2* lines = sm + 512;
    const int tid = threadIdx.x;
    const int u = tid >> 4, t = tid & 15;
    const int pc0 = blockIdx.x * 16;
    const int b = blockIdx.y;

    for (int j = tid; j < 512; j += 256) {
        float sv, cv; sincospif((float)j * (1.0f / 512.0f), &sv, &cv);
        W[j] = make_float2(cv, -sv);
    }
    float2* ls = lines + u * 1026;
    {
        const float2* src = g_Y + ((size_t)(b * PCN + pc0 + u)) * KPAD;
        for (int k = t; k <= 1024; k += 16) ls[k] = src[k];
    }
    __syncthreads();

    // pack 1025 half-spectrum bins -> 1024 complex for half-size inverse FFT.
    // DC/Nyquist imag parts dropped (pocketfft/cuFFT C2R convention).
    const float SCI = 0.04419417382415922f;  // 2/sqrt(2048)
    for (int k = t; k <= 512; k += 16) {
        float2 Xk = ls[k];
        float2 Xj = ls[1024 - k];
        if (k == 0) { Xk.y = 0.f; Xj.y = 0.f; }
        float ex = 0.5f * (Xk.x + Xj.x), ey = 0.5f * (Xk.y - Xj.y);
        float dx = 0.5f * (Xk.x - Xj.x), dy = 0.5f * (Xk.y + Xj.y);
        float sv, cv; sincospif((float)k * (1.0f / 1024.0f), &sv, &cv);
        float ox = cv * dx - sv * dy;
        float oy = cv * dy + sv * dx;
        ls[k] = make_float2(SCI * (ex - oy), SCI * (ey + ox));
        if (k > 0 && k < 512)
            ls[1024 - k] = make_float2(SCI * (ex + oy), SCI * (ox - ey));
    }
    __syncthreads();

    fft1024(ls, W, t, true);   // unnormalized e^{+} sum; scale folded above

    {   // time samples interleaved in ls; add residual and store coalesced
        const float* sf = (const float*)lines;   // line u at float offset u*2052
        const float* xb = x + (size_t)b * LL * PCN + pc0;
        float* ob = out + (size_t)b * LL * PCN + pc0;
        for (int idx = tid; idx < 16 * 512; idx += 256) {
            int l = idx >> 2, q = idx & 3;
            float4 xv = *(const float4*)(xb + (size_t)l * PCN + q * 4);
            int ub = q * 4;
            float4 r;
            r.x = xv.x + sf[(ub + 0) * 2052 + l];
            r.y = xv.y + sf[(ub + 1) * 2052 + l];
            r.z = xv.z + sf[(ub + 2) * 2052 + l];
            r.w = xv.w + sf[(ub + 3) * 2052 + l];
            *(float4*)(ob + (size_t)l * PCN + q * 4) = r;
        }
    }
}

extern "C" void kernel_launch(void* const* d_in, const int* in_sizes, int n_in,
                              void* d_out, int out_size) {
    const float* x  = (const float*)d_in[0];
    const float* w1 = (const float*)d_in[1];
    const float* b1 = (const float*)d_in[2];
    const float* w2 = (const float*)d_in[3];
    const float* b2 = (const float*)d_in[4];
    float* out = (float*)d_out;

    const size_t s1 = (size_t)(16 * 1025 + 512) * sizeof(float2);           // 135,296 B
    const size_t s2 = (size_t)(2 * 4096) * 4 + (4 * 64 * PSTR + 256) * 4;   // 103,424 B
    const size_t s3 = (size_t)(16 * 1026 + 512) * sizeof(float2);           // 135,424 B

    cudaFuncSetAttribute(k_fwd, cudaFuncAttributeMaxDynamicSharedMemorySize, (int)s1);
    cudaFuncSetAttribute(k_mlp, cudaFuncAttributeMaxDynamicSharedMemorySize, (int)s2);
    cudaFuncSetAttribute(k_inv, cudaFuncAttributeMaxDynamicSharedMemorySize, (int)s3);

    k_fwd<<<dim3(PCN / 16, BB), 256, s1>>>(x);
    k_mlp<<<dim3(17, 64, BB), 256, s2>>>(w1, b1, w2, b2);
    k_inv<<<dim3(PCN / 16, BB), 256, s3>>>(x, out);
}

// round 4
// speedup vs baseline: 1.1596x; 1.1596x over previous
#include <cuda_runtime.h>
#include <cuda_bf16.h>
#include <math.h>

// Problem constants
#define BB   4
#define LL   2048
#define LF   1025          // rfft output bins
#define PP   512
#define CC   8
#define PCN  4096          // P*C
#define NBL  8
#define BSZ  64
#define KPAD 1032          // padded line stride in complex elements
#define PSTR 68            // padded plane row stride (floats) in k_mlp; 68*4B = 16B-aligned

typedef unsigned long long u64;

// 135 MB frequency-domain scratch: [b][pc][k] complex, line stride KPAD
__device__ float2 g_Y[(size_t)BB * PCN * KPAD];

// single extern shared symbol, cast per-kernel
extern __shared__ unsigned char smbase[];

// ---------- small helpers ----------
__device__ __forceinline__ u64 pack2(float a, float b) {
    u64 r; asm("mov.b64 %0, {%1, %2};" : "=l"(r) : "f"(a), "f"(b)); return r;
}
__device__ __forceinline__ float2 unpack2(u64 v) {
    float2 r; asm("mov.b64 {%0, %1}, %2;" : "=f"(r.x), "=f"(r.y) : "l"(v)); return r;
}
__device__ __forceinline__ void ffma2(u64& acc, u64 a, u64 b) {
    asm("fma.rn.f32x2 %0, %1, %2, %0;" : "+l"(acc) : "l"(a), "l"(b));
}
__device__ __forceinline__ float gelu_exact(float v) {
    return 0.5f * v * (1.0f + erff(v * 0.7071067811865475f));
}
__device__ __forceinline__ float2 cmulf(float2 x, float2 w) {
    return make_float2(x.x * w.x - x.y * w.y, x.x * w.y + x.y * w.x);
}

// base-4 digit reversal of 5 digits (1024 points)
__device__ __forceinline__ int rev4_10(int j) {
    int r = 0;
    #pragma unroll
    for (int d = 0; d < 5; ++d) { r = (r << 2) | (j & 3); j >>= 2; }
    return r;
}

// In-smem 1024-point complex FFT, radix-4 DIT (5 stages), digit-reversal first.
// ls: line buffer (stride 1). W: e^{-2pi i t/1024}, t<1024. t32: 0..31 lane within line.
// inv=true: conjugated twiddles, W4=+i (unnormalized inverse).
__device__ __forceinline__ void fft1024_r4(float2* ls, const float2* W, int t32, bool inv) {
    for (int j = t32; j < 1024; j += 32) {
        int r = rev4_10(j);
        if (r > j) { float2 a = ls[j]; ls[j] = ls[r]; ls[r] = a; }
    }
    __syncthreads();
    #pragma unroll
    for (int s = 0; s < 5; ++s) {
        const int q4 = 1 << (2 * s);
        const int sh = 8 - 2 * s;
        #pragma unroll 2
        for (int mth = t32; mth < 256; mth += 32) {
            int j = mth & (q4 - 1);
            int i0 = ((mth >> (2 * s)) << (2 * s + 2)) + j;
            int e1 = j << sh;
            float2 w1 = W[e1], w2 = W[2 * e1], w3 = W[3 * e1];
            if (inv) { w1.y = -w1.y; w2.y = -w2.y; w3.y = -w3.y; }
            float2 a = ls[i0];
            float2 b = cmulf(ls[i0 + q4], w1);
            float2 c = cmulf(ls[i0 + 2 * q4], w2);
            float2 d = cmulf(ls[i0 + 3 * q4], w3);
            float2 t0 = make_float2(a.x + c.x, a.y + c.y);
            float2 t1 = make_float2(a.x - c.x, a.y - c.y);
            float2 t2 = make_float2(b.x + d.x, b.y + d.y);
            float2 t3 = make_float2(b.x - d.x, b.y - d.y);
            ls[i0]          = make_float2(t0.x + t2.x, t0.y + t2.y);
            ls[i0 + 2 * q4] = make_float2(t0.x - t2.x, t0.y - t2.y);
            if (!inv) {   // y1 = t1 - i t3 ; y3 = t1 + i t3
                ls[i0 + q4]     = make_float2(t1.x + t3.y, t1.y - t3.x);
                ls[i0 + 3 * q4] = make_float2(t1.x - t3.y, t1.y + t3.x);
            } else {      // y1 = t1 + i t3 ; y3 = t1 - i t3
                ls[i0 + q4]     = make_float2(t1.x - t3.y, t1.y + t3.x);
                ls[i0 + 3 * q4] = make_float2(t1.x + t3.y, t1.y - t3.x);
            }
        }
        __syncthreads();
    }
}

// ---------- K1: forward rfft (fused transpose), 512 threads, 16 lines ----------
__global__ __launch_bounds__(512, 1) void k_fwd(const float* __restrict__ x) {
    float2* sm = (float2*)smbase;
    float2* W = sm;                 // 1024 twiddles
    float2* lines = sm + 1024;      // 16 lines, stride 1025 complex
    const int tid = threadIdx.x;
    const int u = tid >> 5, t = tid & 31;
    const int pc0 = blockIdx.x * 16;
    const int b = blockIdx.y;

    for (int j = tid; j < 1024; j += 512) {
        float sv, cv; sincospif((float)j * (1.0f / 512.0f), &sv, &cv);
        W[j] = make_float2(cv, -sv);
    }
    {   // Coalesced load of 16 lines (float4 across pc)
        float* sf = (float*)lines;                     // line u at float offset u*2050
        const float* xb = x + (size_t)b * LL * PCN + pc0;
        for (int idx = tid; idx < 16 * 512; idx += 512) {
            int l = idx >> 2, q = idx & 3;
            float4 v = *(const float4*)(xb + (size_t)l * PCN + q * 4);
            int ub = q * 4;
            sf[(ub + 0) * 2050 + l] = v.x;
            sf[(ub + 1) * 2050 + l] = v.y;
            sf[(ub + 2) * 2050 + l] = v.z;
            sf[(ub + 3) * 2050 + l] = v.w;
        }
    }
    __syncthreads();

    float2* ls = lines + u * 1025;   // 1024 complex = 2048 reals (even/odd packed)
    fft1024_r4(ls, W, t, false);

    {   // rfft unpack + ortho scale, store (k-contiguous, coalesced)
        float2* out = g_Y + ((size_t)(b * PCN + pc0 + u)) * KPAD;
        const float SC = 0.02209708691207961f;  // 1/sqrt(2048)
        for (int k = t; k <= 1024; k += 32) {
            float2 Zk = ls[k & 1023];
            float2 Zm = ls[(1024 - k) & 1023];
            float er = 0.5f * (Zk.x + Zm.x), ei = 0.5f * (Zk.y - Zm.y);
            float orr = 0.5f * (Zk.y + Zm.y), oi = 0.5f * (Zm.x - Zk.x);
            float sv, cv; sincospif((float)k * (1.0f / 1024.0f), &sv, &cv);
            float xr = er + cv * orr + sv * oi;
            float xi = ei + cv * oi - sv * orr;
            out[k] = make_float2(SC * xr, SC * xi);
        }
    }
}

// ---------- K2: block-diagonal complex MLP, in-place on g_Y ----------
// grid (17 ktiles of 64, 64 = n*8+c, B), 256 threads, occ 2.
// Thread (o, kg): output column o, 16 k's. f32x2 packs over k-pairs.
__global__ __launch_bounds__(256, 2) void k_mlp(const float* __restrict__ w1g,
                                                const float* __restrict__ b1g,
                                                const float* __restrict__ w2g,
                                                const float* __restrict__ b2g) {
    float* sm = (float*)smbase;
    unsigned* Wp1 = (unsigned*)sm;            // 4096: (bf16 w1_0, bf16 w1_1) per (i,o)
    unsigned* Wp2 = Wp1 + 4096;               // 4096
    float* Xr = (float*)(Wp2 + 4096);         // [64][PSTR]
    float* Xi = Xr + 64 * PSTR;
    float* Hr = Xi + 64 * PSTR;
    float* Hi = Hr + 64 * PSTR;
    float* B1r = Hi + 64 * PSTR;
    float* B1i = B1r + 64;
    float* B2r = B1i + 64;
    float* B2i = B2r + 64;

    const int tid = threadIdx.x;
    const int k0 = blockIdx.x * 64;
    const int n = blockIdx.y >> 3, c = blockIdx.y & 7;
    const int b = blockIdx.z;

    for (int idx = tid; idx < 4096; idx += 256) {
        __nv_bfloat162 h1 = __floats2bfloat162_rn(w1g[n * 4096 + idx],
                                                  w1g[32768 + n * 4096 + idx]);
        Wp1[idx] = *(unsigned*)&h1;
        __nv_bfloat162 h2 = __floats2bfloat162_rn(w2g[n * 4096 + idx],
                                                  w2g[32768 + n * 4096 + idx]);
        Wp2[idx] = *(unsigned*)&h2;
    }
    if (tid < 64) {
        B1r[tid] = b1g[n * 64 + tid];  B1i[tid] = b1g[512 + n * 64 + tid];
        B2r[tid] = b2g[n * 64 + tid];  B2i[tid] = b2g[512 + n * 64 + tid];
    }
    const size_t base = ((size_t)b * PCN + (size_t)n * BSZ * CC + c) * KPAD;
    for (int idx = tid; idx < 4096; idx += 256) {
        int i = idx >> 6, kk = idx & 63;
        float2 v = make_float2(0.f, 0.f);
        if (k0 + kk <= 1024) v = g_Y[base + (size_t)i * CC * KPAD + k0 + kk];
        Xr[i * PSTR + kk] = v.x;
        Xi[i * PSTR + kk] = v.y;
    }
    __syncthreads();

    const int o = tid & 63, kg = tid >> 6;
    const int ks = kg * 16;
    u64 ar[8], ai[8];

    // ---- layer 1: acc_r = b1r + X_r W0 - X_i W1 ; acc_i = b1i + X_i W0 + X_r W1
    {
        float brv = B1r[o], biv = B1i[o];
        u64 br = pack2(brv, brv), bi = pack2(biv, biv);
        #pragma unroll
        for (int p = 0; p < 8; ++p) { ar[p] = br; ai[p] = bi; }
    }
    for (int i = 0; i < 64; ++i) {
        unsigned wp = Wp1[i * 64 + o];
        float2 wf = __bfloat1622float2(*(__nv_bfloat162*)&wp);  // (w0, w1)
        u64 p0 = pack2(wf.x, wf.x);
        u64 p1 = pack2(wf.y, wf.y);
        u64 n1 = pack2(-wf.y, -wf.y);
        const ulonglong2* xr4 = (const ulonglong2*)(Xr + i * PSTR + ks);
        const ulonglong2* xi4 = (const ulonglong2*)(Xi + i * PSTR + ks);
        #pragma unroll
        for (int pp = 0; pp < 4; ++pp) {
            ulonglong2 vr = xr4[pp];   // broadcast LDS.128 (2 k-pairs)
            ulonglong2 vi = xi4[pp];
            ffma2(ar[2 * pp],     vr.x, p0);
            ffma2(ar[2 * pp + 1], vr.y, p0);
            ffma2(ar[2 * pp],     vi.x, n1);
            ffma2(ar[2 * pp + 1], vi.y, n1);
            ffma2(ai[2 * pp],     vi.x, p0);
            ffma2(ai[2 * pp + 1], vi.y, p0);
            ffma2(ai[2 * pp],     vr.x, p1);
            ffma2(ai[2 * pp + 1], vr.y, p1);
        }
    }
    // gelu -> H planes
    #pragma unroll
    for (int p = 0; p < 8; ++p) {
        float2 vr = unpack2(ar[p]);
        float2 vi = unpack2(ai[p]);
        vr.x = gelu_exact(vr.x); vr.y = gelu_exact(vr.y);
        vi.x = gelu_exact(vi.x); vi.y = gelu_exact(vi.y);
        *(u64*)(Hr + o * PSTR + ks + 2 * p) = pack2(vr.x, vr.y);
        *(u64*)(Hi + o * PSTR + ks + 2 * p) = pack2(vi.x, vi.y);
    }
    __syncthreads();

    // ---- layer 2
    {
        float brv = B2r[o], biv = B2i[o];
        u64 br = pack2(brv, brv), bi = pack2(biv, biv);
        #pragma unroll
        for (int p = 0; p < 8; ++p) { ar[p] = br; ai[p] = bi; }
    }
    for (int i = 0; i < 64; ++i) {
        unsigned wp = Wp2[i * 64 + o];
        float2 wf = __bfloat1622float2(*(__nv_bfloat162*)&wp);
        u64 p0 = pack2(wf.x, wf.x);
        u64 p1 = pack2(wf.y, wf.y);
        u64 n1 = pack2(-wf.y, -wf.y);
        const ulonglong2* hr4 = (const ulonglong2*)(Hr + i * PSTR + ks);
        const ulonglong2* hi4 = (const ulonglong2*)(Hi + i * PSTR + ks);
        #pragma unroll
        for (int pp = 0; pp < 4; ++pp) {
            ulonglong2 vr = hr4[pp];
            ulonglong2 vi = hi4[pp];
            ffma2(ar[2 * pp],     vr.x, p0);
            ffma2(ar[2 * pp + 1], vr.y, p0);
            ffma2(ar[2 * pp],     vi.x, n1);
            ffma2(ar[2 * pp + 1], vi.y, n1);
            ffma2(ai[2 * pp],     vi.x, p0);
            ffma2(ai[2 * pp + 1], vi.y, p0);
            ffma2(ai[2 * pp],     vr.x, p1);
            ffma2(ai[2 * pp + 1], vr.y, p1);
        }
    }
    // store outputs into X planes (dead after layer 1)
    #pragma unroll
    for (int p = 0; p < 8; ++p) {
        *(u64*)(Xr + o * PSTR + ks + 2 * p) = ar[p];
        *(u64*)(Xi + o * PSTR + ks + 2 * p) = ai[p];
    }
    __syncthreads();
    for (int idx = tid; idx < 4096; idx += 256) {
        int i = idx >> 6, kk = idx & 63;
        if (k0 + kk <= 1024)
            g_Y[base + (size_t)i * CC * KPAD + k0 + kk] =
                make_float2(Xr[i * PSTR + kk], Xi[i * PSTR + kk]);
    }
}

// ---------- K3: inverse rfft + residual (fused transpose back), 512 threads ----------
__global__ __launch_bounds__(512, 1) void k_inv(const float* __restrict__ x,
                                                float* __restrict__ out) {
    float2* sm = (float2*)smbase;
    float2* W = sm;                 // 1024 twiddles
    float2* lines = sm + 1024;      // 16 lines, stride 1026 complex
    const int tid = threadIdx.x;
    const int u = tid >> 5, t = tid & 31;
    const int pc0 = blockIdx.x * 16;
    const int b = blockIdx.y;

    for (int j = tid; j < 1024; j += 512) {
        float sv, cv; sincospif((float)j * (1.0f / 512.0f), &sv, &cv);
        W[j] = make_float2(cv, -sv);
    }
    float2* ls = lines + u * 1026;
    {
        const float2* src = g_Y + ((size_t)(b * PCN + pc0 + u)) * KPAD;
        for (int k = t; k <= 1024; k += 32) ls[k] = src[k];
    }
    __syncthreads();

    // pack 1025 half-spectrum bins -> 1024 complex for half-size inverse FFT.
    // DC/Nyquist imag parts dropped (pocketfft/cuFFT C2R convention).
    const float SCI = 0.04419417382415922f;  // 2/sqrt(2048)
    for (int k = t; k <= 512; k += 32) {
        float2 Xk = ls[k];
        float2 Xj = ls[1024 - k];
        if (k == 0) { Xk.y = 0.f; Xj.y = 0.f; }
        float ex = 0.5f * (Xk.x + Xj.x), ey = 0.5f * (Xk.y - Xj.y);
        float dx = 0.5f * (Xk.x - Xj.x), dy = 0.5f * (Xk.y + Xj.y);
        float sv, cv; sincospif((float)k * (1.0f / 1024.0f), &sv, &cv);
        float ox = cv * dx - sv * dy;
        float oy = cv * dy + sv * dx;
        ls[k] = make_float2(SCI * (ex - oy), SCI * (ey + ox));
        if (k > 0 && k < 512)
            ls[1024 - k] = make_float2(SCI * (ex + oy), SCI * (ox - ey));
    }
    __syncthreads();

    fft1024_r4(ls, W, t, true);   // unnormalized e^{+} sum; scale folded above

    {   // time samples interleaved in ls; add residual and store coalesced
        const float* sf = (const float*)lines;   // line u at float offset u*2052
        const float* xb = x + (size_t)b * LL * PCN + pc0;
        float* ob = out + (size_t)b * LL * PCN + pc0;
        for (int idx = tid; idx < 16 * 512; idx += 512) {
            int l = idx >> 2, q = idx & 3;
            float4 xv = *(const float4*)(xb + (size_t)l * PCN + q * 4);
            int ub = q * 4;
            float4 r;
            r.x = xv.x + sf[(ub + 0) * 2052 + l];
            r.y = xv.y + sf[(ub + 1) * 2052 + l];
            r.z = xv.z + sf[(ub + 2) * 2052 + l];
            r.w = xv.w + sf[(ub + 3) * 2052 + l];
            *(float4*)(ob + (size_t)l * PCN + q * 4) = r;
        }
    }
}

extern "C" void kernel_launch(void* const* d_in, const int* in_sizes, int n_in,
                              void* d_out, int out_size) {
    const float* x  = (const float*)d_in[0];
    const float* w1 = (const float*)d_in[1];
    const float* b1 = (const float*)d_in[2];
    const float* w2 = (const float*)d_in[3];
    const float* b2 = (const float*)d_in[4];
    float* out = (float*)d_out;

    const size_t s1 = (size_t)(1024 + 16 * 1025) * sizeof(float2);          // 139,392 B
    const size_t s2 = (size_t)(2 * 4096) * 4 + (4 * 64 * PSTR + 256) * 4;   // 103,424 B
    const size_t s3 = (size_t)(1024 + 16 * 1026) * sizeof(float2);          // 139,520 B

    cudaFuncSetAttribute(k_fwd, cudaFuncAttributeMaxDynamicSharedMemorySize, (int)s1);
    cudaFuncSetAttribute(k_mlp, cudaFuncAttributeMaxDynamicSharedMemorySize, (int)s2);
    cudaFuncSetAttribute(k_inv, cudaFuncAttributeMaxDynamicSharedMemorySize, (int)s3);

    k_fwd<<<dim3(PCN / 16, BB), 512, s1>>>(x);
    k_mlp<<<dim3(17, 64, BB), 256, s2>>>(w1, b1, w2, b2);
    k_inv<<<dim3(PCN / 16, BB), 512, s3>>>(x, out);
}

// round 5
// speedup vs baseline: 1.5864x; 1.3680x over previous
#include <cuda_runtime.h>
#include <cuda_bf16.h>
#include <math.h>

// Problem constants
#define BB   4
#define LL   2048
#define LF   1025          // rfft output bins
#define PP   512
#define CC   8
#define PCN  4096          // P*C
#define NBL  8
#define BSZ  64
#define KPAD 1032          // padded line stride in complex elements
#define PSTR 68            // padded plane row stride (floats) in k_mlp

// bank-decorrelating bijection on line-buffer indices (works for k<=1024)
#define PHY(k) ((k) ^ (((k) >> 4) & 15))

typedef unsigned long long u64;

// 135 MB frequency-domain scratch: [b][pc][k] complex, line stride KPAD
__device__ float2 g_Y[(size_t)BB * PCN * KPAD];

// single extern shared symbol, cast per-kernel
extern __shared__ unsigned char smbase[];

// ---------- small helpers ----------
__device__ __forceinline__ u64 pack2(float a, float b) {
    u64 r; asm("mov.b64 %0, {%1, %2};" : "=l"(r) : "f"(a), "f"(b)); return r;
}
__device__ __forceinline__ float2 unpack2(u64 v) {
    float2 r; asm("mov.b64 {%0, %1}, %2;" : "=f"(r.x), "=f"(r.y) : "l"(v)); return r;
}
__device__ __forceinline__ void ffma2(u64& acc, u64 a, u64 b) {
    asm("fma.rn.f32x2 %0, %1, %2, %0;" : "+l"(acc) : "l"(a), "l"(b));
}
__device__ __forceinline__ float gelu_exact(float v) {
    return 0.5f * v * (1.0f + erff(v * 0.7071067811865475f));
}
__device__ __forceinline__ float2 cmulf(float2 x, float2 w) {
    return make_float2(x.x * w.x - x.y * w.y, x.x * w.y + x.y * w.x);
}
__device__ __forceinline__ float2 ldw(const float2* W, int e, bool inv) {
    float2 w = W[e];
    if (inv) w.y = -w.y;
    return w;
}
// radix-4 DIT butterfly: inputs (a,b,c,d) at group positions 0..3, twiddled by w1..w3,
// outputs written back to same slots (pos 0..3). Forward: W4 = -i ; inverse: +i.
__device__ __forceinline__ void bfly4(float2& a, float2& b, float2& c, float2& d,
                                      float2 w1, float2 w2, float2 w3, bool inv) {
    float2 B = cmulf(b, w1), C = cmulf(c, w2), D = cmulf(d, w3);
    float2 t0 = make_float2(a.x + C.x, a.y + C.y);
    float2 t1 = make_float2(a.x - C.x, a.y - C.y);
    float2 t2 = make_float2(B.x + D.x, B.y + D.y);
    float2 t3 = make_float2(B.x - D.x, B.y - D.y);
    a = make_float2(t0.x + t2.x, t0.y + t2.y);
    c = make_float2(t0.x - t2.x, t0.y - t2.y);
    if (!inv) { b = make_float2(t1.x + t3.y, t1.y - t3.x);
                d = make_float2(t1.x - t3.y, t1.y + t3.x); }
    else      { b = make_float2(t1.x - t3.y, t1.y + t3.x);
                d = make_float2(t1.x + t3.y, t1.y - t3.x); }
}
// no-twiddle variant (all twiddles = 1)
__device__ __forceinline__ void bfly4n(float2& a, float2& b, float2& c, float2& d, bool inv) {
    float2 t0 = make_float2(a.x + c.x, a.y + c.y);
    float2 t1 = make_float2(a.x - c.x, a.y - c.y);
    float2 t2 = make_float2(b.x + d.x, b.y + d.y);
    float2 t3 = make_float2(b.x - d.x, b.y - d.y);
    a = make_float2(t0.x + t2.x, t0.y + t2.y);
    c = make_float2(t0.x - t2.x, t0.y - t2.y);
    if (!inv) { b = make_float2(t1.x + t3.y, t1.y - t3.x);
                d = make_float2(t1.x - t3.y, t1.y + t3.x); }
    else      { b = make_float2(t1.x - t3.y, t1.y + t3.x);
                d = make_float2(t1.x + t3.y, t1.y - t3.x); }
}

// In-smem 1024-point complex FFT. 64 threads per line (t = 0..63).
// 3 passes: P1 = fused radix-4 stages 0,1 with digit-reversed loads;
// P2 = fused stages 2,3; P3 = stage 4. All smem accesses through PHY().
// Caller must __syncthreads() before entry (data staged at PHY positions).
__device__ __forceinline__ void fft1024_f(float2* ls, const float2* W, int t, bool inv) {
    // ---- P1: stages 0,1 (q=1). unit i0 = 16t. e1 = 0, e2_r = r<<6.
    {
        const int i0 = t << 4;
        const int rt = ((t & 3) << 4) | (((t >> 2) & 3) << 2) | (t >> 4);
        float2 x[16];
        #pragma unroll
        for (int m = 0; m < 16; ++m) {
            int li = rt + ((m & 3) << 8) + ((m >> 2) << 6);  // digit-reversed source
            x[m] = ls[PHY(li)];
        }
        #pragma unroll
        for (int a = 0; a < 4; ++a)
            bfly4n(x[4 * a], x[4 * a + 1], x[4 * a + 2], x[4 * a + 3], inv);
        #pragma unroll
        for (int r = 1; r < 4; ++r) {
            int e2 = r << 6;
            bfly4(x[r], x[4 + r], x[8 + r], x[12 + r],
                  ldw(W, e2, inv), ldw(W, 2 * e2, inv), ldw(W, 3 * e2, inv), inv);
        }
        bfly4n(x[0], x[4], x[8], x[12], inv);   // r = 0 has unit twiddles
        #pragma unroll
        for (int m = 0; m < 16; ++m) ls[PHY(i0 + m)] = x[m];
    }
    __syncthreads();
    // ---- P2: stages 2,3 (q=16). i0 = (t>>4)*256 + (t&15).
    {
        const int j = t & 15;
        const int i0 = ((t >> 4) << 8) + j;
        float2 x[16];
        #pragma unroll
        for (int m = 0; m < 16; ++m) x[m] = ls[PHY(i0 + (m << 4))];
        const int e1 = j << 4;
        {
            float2 w1 = ldw(W, e1, inv), w2 = ldw(W, 2 * e1, inv), w3 = ldw(W, 3 * e1, inv);
            #pragma unroll
            for (int a = 0; a < 4; ++a)
                bfly4(x[4 * a], x[4 * a + 1], x[4 * a + 2], x[4 * a + 3], w1, w2, w3, inv);
        }
        #pragma unroll
        for (int r = 0; r < 4; ++r) {
            int e2 = (j << 2) + (r << 6);
            bfly4(x[r], x[4 + r], x[8 + r], x[12 + r],
                  ldw(W, e2, inv), ldw(W, 2 * e2, inv), ldw(W, 3 * e2, inv), inv);
        }
        #pragma unroll
        for (int m = 0; m < 16; ++m) ls[PHY(i0 + (m << 4))] = x[m];
    }
    __syncthreads();
    // ---- P3: stage 4 (q=256), 4 butterflies per thread.
    #pragma unroll
    for (int it = 0; it < 4; ++it) {
        int j = t + (it << 6);
        float2 w1 = ldw(W, j, inv), w2 = ldw(W, 2 * j, inv), w3 = ldw(W, 3 * j, inv);
        float2 a = ls[PHY(j)], b = ls[PHY(j + 256)], c = ls[PHY(j + 512)], d = ls[PHY(j + 768)];
        bfly4(a, b, c, d, w1, w2, w3, inv);
        ls[PHY(j)] = a; ls[PHY(j + 256)] = b; ls[PHY(j + 512)] = c; ls[PHY(j + 768)] = d;
    }
    __syncthreads();
}

// ---------- K1: forward rfft (fused transpose), 256 threads, 4 lines ----------
__global__ __launch_bounds__(256, 3) void k_fwd(const float* __restrict__ x) {
    float2* sm = (float2*)smbase;
    float2* W = sm;                 // 1024 twiddles
    float2* lines = sm + 1024;      // 4 lines, stride 1025 complex
    const int tid = threadIdx.x;
    const int u = tid >> 6, t = tid & 63;
    const int pc0 = blockIdx.x * 4;
    const int b = blockIdx.y;

    for (int j = tid; j < 1024; j += 256) {
        float sv, cv; sincospif((float)j * (1.0f / 512.0f), &sv, &cv);
        W[j] = make_float2(cv, -sv);
    }
    {   // fill: one float4 per time-index l covers the 4 lines (pc0..pc0+3).
        // even/odd packing: float sample l -> complex element p=l>>1, comp=l&1,
        // stored at PHY(p) (conflict-free: verified 32 distinct banks per STS).
        const float* xb = x + (size_t)b * LL * PCN + pc0;
        for (int l = tid; l < 2048; l += 256) {
            float4 v = *(const float4*)(xb + (size_t)l * PCN);
            int fo = 2 * PHY(l >> 1) + (l & 1);
            float* s0 = (float*)lines;
            s0[0 * 2050 + fo] = v.x;
            s0[1 * 2050 + fo] = v.y;
            s0[2 * 2050 + fo] = v.z;
            s0[3 * 2050 + fo] = v.w;
        }
    }
    __syncthreads();

    float2* ls = lines + u * 1025;
    fft1024_f(ls, W, t, false);

    {   // rfft unpack + ortho scale, store (k-contiguous, coalesced)
        float2* out = g_Y + ((size_t)(b * PCN + pc0 + u)) * KPAD;
        const float SC = 0.02209708691207961f;  // 1/sqrt(2048)
        for (int k = t; k <= 1024; k += 64) {
            float2 Zk = ls[PHY(k & 1023)];
            float2 Zm = ls[PHY((1024 - k) & 1023)];
            float er = 0.5f * (Zk.x + Zm.x), ei = 0.5f * (Zk.y - Zm.y);
            float orr = 0.5f * (Zk.y + Zm.y), oi = 0.5f * (Zm.x - Zk.x);
            float sv, cv; sincospif((float)k * (1.0f / 1024.0f), &sv, &cv);
            float xr = er + cv * orr + sv * oi;
            float xi = ei + cv * oi - sv * orr;
            out[k] = make_float2(SC * xr, SC * xi);
        }
    }
}

// ---------- K2: block-diagonal complex MLP, in-place on g_Y ----------
__global__ __launch_bounds__(256, 2) void k_mlp(const float* __restrict__ w1g,
                                                const float* __restrict__ b1g,
                                                const float* __restrict__ w2g,
                                                const float* __restrict__ b2g) {
    float* sm = (float*)smbase;
    unsigned* Wp1 = (unsigned*)sm;            // 4096: (bf16 w1_0, bf16 w1_1) per (i,o)
    unsigned* Wp2 = Wp1 + 4096;               // 4096
    float* Xr = (float*)(Wp2 + 4096);         // [64][PSTR]
    float* Xi = Xr + 64 * PSTR;
    float* Hr = Xi + 64 * PSTR;
    float* Hi = Hr + 64 * PSTR;
    float* B1r = Hi + 64 * PSTR;
    float* B1i = B1r + 64;
    float* B2r = B1i + 64;
    float* B2i = B2r + 64;

    const int tid = threadIdx.x;
    const int k0 = blockIdx.x * 64;
    const int n = blockIdx.y >> 3, c = blockIdx.y & 7;
    const int b = blockIdx.z;

    for (int idx = tid; idx < 4096; idx += 256) {
        __nv_bfloat162 h1 = __floats2bfloat162_rn(w1g[n * 4096 + idx],
                                                  w1g[32768 + n * 4096 + idx]);
        Wp1[idx] = *(unsigned*)&h1;
        __nv_bfloat162 h2 = __floats2bfloat162_rn(w2g[n * 4096 + idx],
                                                  w2g[32768 + n * 4096 + idx]);
        Wp2[idx] = *(unsigned*)&h2;
    }
    if (tid < 64) {
        B1r[tid] = b1g[n * 64 + tid];  B1i[tid] = b1g[512 + n * 64 + tid];
        B2r[tid] = b2g[n * 64 + tid];  B2i[tid] = b2g[512 + n * 64 + tid];
    }
    const size_t base = ((size_t)b * PCN + (size_t)n * BSZ * CC + c) * KPAD;
    for (int idx = tid; idx < 4096; idx += 256) {
        int i = idx >> 6, kk = idx & 63;
        float2 v = make_float2(0.f, 0.f);
        if (k0 + kk <= 1024) v = g_Y[base + (size_t)i * CC * KPAD + k0 + kk];
        Xr[i * PSTR + kk] = v.x;
        Xi[i * PSTR + kk] = v.y;
    }
    __syncthreads();

    const int o = tid & 63, kg = tid >> 6;
    const int ks = kg * 16;
    u64 ar[8], ai[8];

    // ---- layer 1
    {
        float brv = B1r[o], biv = B1i[o];
        u64 br = pack2(brv, brv), bi = pack2(biv, biv);
        #pragma unroll
        for (int p = 0; p < 8; ++p) { ar[p] = br; ai[p] = bi; }
    }
    for (int i = 0; i < 64; ++i) {
        unsigned wp = Wp1[i * 64 + o];
        float2 wf = __bfloat1622float2(*(__nv_bfloat162*)&wp);
        u64 p0 = pack2(wf.x, wf.x);
        u64 p1 = pack2(wf.y, wf.y);
        u64 n1 = pack2(-wf.y, -wf.y);
        const ulonglong2* xr4 = (const ulonglong2*)(Xr + i * PSTR + ks);
        const ulonglong2* xi4 = (const ulonglong2*)(Xi + i * PSTR + ks);
        #pragma unroll
        for (int pp = 0; pp < 4; ++pp) {
            ulonglong2 vr = xr4[pp];
            ulonglong2 vi = xi4[pp];
            ffma2(ar[2 * pp],     vr.x, p0);
            ffma2(ar[2 * pp + 1], vr.y, p0);
            ffma2(ar[2 * pp],     vi.x, n1);
            ffma2(ar[2 * pp + 1], vi.y, n1);
            ffma2(ai[2 * pp],     vi.x, p0);
            ffma2(ai[2 * pp + 1], vi.y, p0);
            ffma2(ai[2 * pp],     vr.x, p1);
            ffma2(ai[2 * pp + 1], vr.y, p1);
        }
    }
    #pragma unroll
    for (int p = 0; p < 8; ++p) {
        float2 vr = unpack2(ar[p]);
        float2 vi = unpack2(ai[p]);
        vr.x = gelu_exact(vr.x); vr.y = gelu_exact(vr.y);
        vi.x = gelu_exact(vi.x); vi.y = gelu_exact(vi.y);
        *(u64*)(Hr + o * PSTR + ks + 2 * p) = pack2(vr.x, vr.y);
        *(u64*)(Hi + o * PSTR + ks + 2 * p) = pack2(vi.x, vi.y);
    }
    __syncthreads();

    // ---- layer 2
    {
        float brv = B2r[o], biv = B2i[o];
        u64 br = pack2(brv, brv), bi = pack2(biv, biv);
        #pragma unroll
        for (int p = 0; p < 8; ++p) { ar[p] = br; ai[p] = bi; }
    }
    for (int i = 0; i < 64; ++i) {
        unsigned wp = Wp2[i * 64 + o];
        float2 wf = __bfloat1622float2(*(__nv_bfloat162*)&wp);
        u64 p0 = pack2(wf.x, wf.x);
        u64 p1 = pack2(wf.y, wf.y);
        u64 n1 = pack2(-wf.y, -wf.y);
        const ulonglong2* hr4 = (const ulonglong2*)(Hr + i * PSTR + ks);
        const ulonglong2* hi4 = (const ulonglong2*)(Hi + i * PSTR + ks);
        #pragma unroll
        for (int pp = 0; pp < 4; ++pp) {
            ulonglong2 vr = hr4[pp];
            ulonglong2 vi = hi4[pp];
            ffma2(ar[2 * pp],     vr.x, p0);
            ffma2(ar[2 * pp + 1], vr.y, p0);
            ffma2(ar[2 * pp],     vi.x, n1);
            ffma2(ar[2 * pp + 1], vi.y, n1);
            ffma2(ai[2 * pp],     vi.x, p0);
            ffma2(ai[2 * pp + 1], vi.y, p0);
            ffma2(ai[2 * pp],     vr.x, p1);
            ffma2(ai[2 * pp + 1], vr.y, p1);
        }
    }
    #pragma unroll
    for (int p = 0; p < 8; ++p) {
        *(u64*)(Xr + o * PSTR + ks + 2 * p) = ar[p];
        *(u64*)(Xi + o * PSTR + ks + 2 * p) = ai[p];
    }
    __syncthreads();
    for (int idx = tid; idx < 4096; idx += 256) {
        int i = idx >> 6, kk = idx & 63;
        if (k0 + kk <= 1024)
            g_Y[base + (size_t)i * CC * KPAD + k0 + kk] =
                make_float2(Xr[i * PSTR + kk], Xi[i * PSTR + kk]);
    }
}

// ---------- K3: inverse rfft + residual (fused transpose back), 4 lines ----------
__global__ __launch_bounds__(256, 3) void k_inv(const float* __restrict__ x,
                                                float* __restrict__ out) {
    float2* sm = (float2*)smbase;
    float2* W = sm;                 // 1024 twiddles
    float2* lines = sm + 1024;      // 4 lines, stride 1026 complex
    const int tid = threadIdx.x;
    const int u = tid >> 6, t = tid & 63;
    const int pc0 = blockIdx.x * 4;
    const int b = blockIdx.y;

    for (int j = tid; j < 1024; j += 256) {
        float sv, cv; sincospif((float)j * (1.0f / 512.0f), &sv, &cv);
        W[j] = make_float2(cv, -sv);
    }
    float2* ls = lines + u * 1026;
    {
        const float2* src = g_Y + ((size_t)(b * PCN + pc0 + u)) * KPAD;
        for (int k = t; k <= 1024; k += 64) ls[PHY(k)] = src[k];
    }
    __syncthreads();

    // pack 1025 half-spectrum bins -> 1024 complex for half-size inverse FFT.
    // DC/Nyquist imag parts dropped (pocketfft/cuFFT C2R convention).
    const float SCI = 0.04419417382415922f;  // 2/sqrt(2048)
    for (int k = t; k <= 512; k += 64) {
        float2 Xk = ls[PHY(k)];
        float2 Xj = ls[PHY(1024 - k)];
        if (k == 0) { Xk.y = 0.f; Xj.y = 0.f; }
        float ex = 0.5f * (Xk.x + Xj.x), ey = 0.5f * (Xk.y - Xj.y);
        float dx = 0.5f * (Xk.x - Xj.x), dy = 0.5f * (Xk.y + Xj.y);
        float sv, cv; sincospif((float)k * (1.0f / 1024.0f), &sv, &cv);
        float ox = cv * dx - sv * dy;
        float oy = cv * dy + sv * dx;
        ls[PHY(k)] = make_float2(SCI * (ex - oy), SCI * (ey + ox));
        if (k > 0 && k < 512)
            ls[PHY(1024 - k)] = make_float2(SCI * (ex + oy), SCI * (ox - ey));
    }
    __syncthreads();

    fft1024_f(ls, W, t, true);   // unnormalized e^{+} sum; scale folded above

    {   // time samples (even/odd packed at PHY positions); residual add, coalesced store
        const float* s0 = (const float*)lines;   // line u at float offset u*2052
        const float* xb = x + (size_t)b * LL * PCN + pc0;
        float* ob = out + (size_t)b * LL * PCN + pc0;
        for (int l = tid; l < 2048; l += 256) {
            float4 xv = *(const float4*)(xb + (size_t)l * PCN);
            int fo = 2 * PHY(l >> 1) + (l & 1);
            float4 r;
            r.x = xv.x + s0[0 * 2052 + fo];
            r.y = xv.y + s0[1 * 2052 + fo];
            r.z = xv.z + s0[2 * 2052 + fo];
            r.w = xv.w + s0[3 * 2052 + fo];
            *(float4*)(ob + (size_t)l * PCN) = r;
        }
    }
}

extern "C" void kernel_launch(void* const* d_in, const int* in_sizes, int n_in,
                              void* d_out, int out_size) {
    const float* x  = (const float*)d_in[0];
    const float* w1 = (const float*)d_in[1];
    const float* b1 = (const float*)d_in[2];
    const float* w2 = (const float*)d_in[3];
    const float* b2 = (const float*)d_in[4];
    float* out = (float*)d_out;

    const size_t s1 = (size_t)(1024 + 4 * 1025) * sizeof(float2);           // 40,992 B
    const size_t s2 = (size_t)(2 * 4096) * 4 + (4 * 64 * PSTR + 256) * 4;   // 103,424 B
    const size_t s3 = (size_t)(1024 + 4 * 1026) * sizeof(float2);           // 41,024 B

    cudaFuncSetAttribute(k_fwd, cudaFuncAttributeMaxDynamicSharedMemorySize, (int)s1);
    cudaFuncSetAttribute(k_mlp, cudaFuncAttributeMaxDynamicSharedMemorySize, (int)s2);
    cudaFuncSetAttribute(k_inv, cudaFuncAttributeMaxDynamicSharedMemorySize, (int)s3);

    k_fwd<<<dim3(PCN / 4, BB), 256, s1>>>(x);
    k_mlp<<<dim3(17, 64, BB), 256, s2>>>(w1, b1, w2, b2);
    k_inv<<<dim3(PCN / 4, BB), 256, s3>>>(x, out);
}

// round 7
// speedup vs baseline: 2.1803x; 1.3744x over previous
#include <cuda_runtime.h>
#include <cuda_bf16.h>
#include <math.h>
#include <cstdint>

// Problem constants
#define BB   4
#define LL   2048
#define LF   1025
#define PP   512
#define CC   8
#define PCN  4096
#define NBL  8
#define BSZ  64
#define KPAD 1032
#define PHY(k) ((k) ^ (((k) >> 4) & 15))

typedef unsigned long long u64;

__device__ float2 g_Y[(size_t)BB * PCN * KPAD];
// packed weight images: [layer][n][o=128][kk-pair word=64] bf16x2
__device__ uint32_t g_Wimg[2 * 8 * 8192];

extern __shared__ unsigned char smbase[];

// ---------- helpers ----------
__device__ __forceinline__ float gelu_exact(float v) {
    return 0.5f * v * (1.0f + erff(v * 0.7071067811865475f));
}
__device__ __forceinline__ float2 cmulf(float2 x, float2 w) {
    return make_float2(x.x * w.x - x.y * w.y, x.x * w.y + x.y * w.x);
}
__device__ __forceinline__ float2 ldwt(const float2* W, int e, bool inv) {
    float2 w = W[e]; if (inv) w.y = -w.y; return w;
}
__device__ __forceinline__ void bfly4(float2& a, float2& b, float2& c, float2& d,
                                      float2 w1, float2 w2, float2 w3, bool inv) {
    float2 B = cmulf(b, w1), C = cmulf(c, w2), D = cmulf(d, w3);
    float2 t0 = make_float2(a.x + C.x, a.y + C.y);
    float2 t1 = make_float2(a.x - C.x, a.y - C.y);
    float2 t2 = make_float2(B.x + D.x, B.y + D.y);
    float2 t3 = make_float2(B.x - D.x, B.y - D.y);
    a = make_float2(t0.x + t2.x, t0.y + t2.y);
    c = make_float2(t0.x - t2.x, t0.y - t2.y);
    if (!inv) { b = make_float2(t1.x + t3.y, t1.y - t3.x);
                d = make_float2(t1.x - t3.y, t1.y + t3.x); }
    else      { b = make_float2(t1.x - t3.y, t1.y + t3.x);
                d = make_float2(t1.x + t3.y, t1.y - t3.x); }
}
__device__ __forceinline__ void bfly4n(float2& a, float2& b, float2& c, float2& d, bool inv) {
    float2 t0 = make_float2(a.x + c.x, a.y + c.y);
    float2 t1 = make_float2(a.x - c.x, a.y - c.y);
    float2 t2 = make_float2(b.x + d.x, b.y + d.y);
    float2 t3 = make_float2(b.x - d.x, b.y - d.y);
    a = make_float2(t0.x + t2.x, t0.y + t2.y);
    c = make_float2(t0.x - t2.x, t0.y - t2.y);
    if (!inv) { b = make_float2(t1.x + t3.y, t1.y - t3.x);
                d = make_float2(t1.x - t3.y, t1.y + t3.x); }
    else      { b = make_float2(t1.x - t3.y, t1.y + t3.x);
                d = make_float2(t1.x + t3.y, t1.y - t3.x); }
}
__device__ __forceinline__ uint32_t pkbf(float a, float b) {
    __nv_bfloat162 h = __floats2bfloat162_rn(a, b);
    return *(uint32_t*)&h;
}
__device__ __forceinline__ void mma16816(float* d, uint32_t a0, uint32_t a1,
                                         uint32_t a2, uint32_t a3,
                                         uint32_t b0, uint32_t b1) {
    asm volatile("mma.sync.aligned.m16n8k16.row.col.f32.bf16.bf16.f32 "
                 "{%0,%1,%2,%3}, {%4,%5,%6,%7}, {%8,%9}, {%0,%1,%2,%3};"
                 : "+f"(d[0]), "+f"(d[1]), "+f"(d[2]), "+f"(d[3])
                 : "r"(a0), "r"(a1), "r"(a2), "r"(a3), "r"(b0), "r"(b1));
}

// In-smem 1024-point FFT (R5 passing version): 3 passes, PHY bank swizzle. t = 0..63.
__device__ __forceinline__ void fft1024_f(float2* ls, const float2* W, int t, bool inv) {
    {
        const int i0 = t << 4;
        const int rt = ((t & 3) << 4) | (((t >> 2) & 3) << 2) | (t >> 4);
        float2 x[16];
        #pragma unroll
        for (int m = 0; m < 16; ++m)
            x[m] = ls[PHY(rt + ((m & 3) << 8) + ((m >> 2) << 6))];
        #pragma unroll
        for (int a = 0; a < 4; ++a)
            bfly4n(x[4 * a], x[4 * a + 1], x[4 * a + 2], x[4 * a + 3], inv);
        #pragma unroll
        for (int r = 1; r < 4; ++r) {
            int e2 = r << 6;
            bfly4(x[r], x[4 + r], x[8 + r], x[12 + r],
                  ldwt(W, e2, inv), ldwt(W, 2 * e2, inv), ldwt(W, 3 * e2, inv), inv);
        }
        bfly4n(x[0], x[4], x[8], x[12], inv);
        #pragma unroll
        for (int m = 0; m < 16; ++m) ls[PHY(i0 + m)] = x[m];
    }
    __syncthreads();
    {
        const int j = t & 15;
        const int i0 = ((t >> 4) << 8) + j;
        float2 x[16];
        #pragma unroll
        for (int m = 0; m < 16; ++m) x[m] = ls[PHY(i0 + (m << 4))];
        const int e1 = j << 4;
        {
            float2 w1 = ldwt(W, e1, inv), w2 = ldwt(W, 2 * e1, inv), w3 = ldwt(W, 3 * e1, inv);
            #pragma unroll
            for (int a = 0; a < 4; ++a)
                bfly4(x[4 * a], x[4 * a + 1], x[4 * a + 2], x[4 * a + 3], w1, w2, w3, inv);
        }
        #pragma unroll
        for (int r = 0; r < 4; ++r) {
            int e2 = (j << 2) + (r << 6);
            bfly4(x[r], x[4 + r], x[8 + r], x[12 + r],
                  ldwt(W, e2, inv), ldwt(W, 2 * e2, inv), ldwt(W, 3 * e2, inv), inv);
        }
        #pragma unroll
        for (int m = 0; m < 16; ++m) ls[PHY(i0 + (m << 4))] = x[m];
    }
    __syncthreads();
    #pragma unroll
    for (int it = 0; it < 4; ++it) {
        int j = t + (it << 6);
        float2 w1 = ldwt(W, j, inv), w2 = ldwt(W, 2 * j, inv), w3 = ldwt(W, 3 * j, inv);
        float2 a = ls[PHY(j)], b = ls[PHY(j + 256)], c = ls[PHY(j + 512)], d = ls[PHY(j + 768)];
        bfly4(a, b, c, d, w1, w2, w3, inv);
        ls[PHY(j)] = a; ls[PHY(j + 256)] = b; ls[PHY(j + 512)] = c; ls[PHY(j + 768)] = d;
    }
    __syncthreads();
}

// ---------- K0: pack weight images ----------
// Bbar[o][kk]: o<64:  kk<64 ? W0[kk][o]        : -W1[kk-64][o]
//              o>=64: kk<64 ? W1[kk][o-64]     :  W0[kk-64][o-64]
// image word [o][w] = bf16x2(Bbar[o][2w], Bbar[o][2w+1])
__global__ void k_wprep(const float* __restrict__ w1g, const float* __restrict__ w2g) {
    const int n = blockIdx.x, l = blockIdx.y;
    const float* wg = l ? w2g : w1g;
    uint32_t* dst = g_Wimg + (size_t)(l * 8 + n) * 8192;
    for (int idx = threadIdx.x; idx < 8192; idx += 256) {
        int o = idx >> 6, wd = idx & 63;
        float v[2];
        #pragma unroll
        for (int q = 0; q < 2; ++q) {
            int kk = 2 * wd + q;
            if (o < 64)
                v[q] = (kk < 64) ? wg[n * 4096 + kk * 64 + o]
                                 : -wg[32768 + n * 4096 + (kk - 64) * 64 + o];
            else
                v[q] = (kk < 64) ? wg[32768 + n * 4096 + kk * 64 + (o - 64)]
                                 : wg[n * 4096 + (kk - 64) * 64 + (o - 64)];
        }
        dst[idx] = pkbf(v[0], v[1]);
    }
}

// ---------- K1: forward rfft ----------
__global__ __launch_bounds__(256, 3) void k_fwd(const float* __restrict__ x) {
    float2* sm = (float2*)smbase;
    float2* W = sm;
    float2* lines = sm + 1024;
    const int tid = threadIdx.x;
    const int u = tid >> 6, t = tid & 63;
    const int pc0 = blockIdx.x * 4;
    const int b = blockIdx.y;

    for (int j = tid; j < 1024; j += 256) {
        float sv, cv; sincospif((float)j * (1.0f / 512.0f), &sv, &cv);
        W[j] = make_float2(cv, -sv);
    }
    {
        const float* xb = x + (size_t)b * LL * PCN + pc0;
        for (int l = tid; l < 2048; l += 256) {
            float4 v = *(const float4*)(xb + (size_t)l * PCN);
            int fo = 2 * PHY(l >> 1) + (l & 1);
            float* s0 = (float*)lines;
            s0[0 * 2050 + fo] = v.x;
            s0[1 * 2050 + fo] = v.y;
            s0[2 * 2050 + fo] = v.z;
            s0[3 * 2050 + fo] = v.w;
        }
    }
    __syncthreads();

    float2* ls = lines + u * 1025;
    fft1024_f(ls, W, t, false);

    {
        float2* out = g_Y + ((size_t)(b * PCN + pc0 + u)) * KPAD;
        const float SC = 0.02209708691207961f;
        for (int k = t; k <= 1024; k += 64) {
            float2 Zk = ls[PHY(k & 1023)];
            float2 Zm = ls[PHY((1024 - k) & 1023)];
            float er = 0.5f * (Zk.x + Zm.x), ei = 0.5f * (Zk.y - Zm.y);
            float orr = 0.5f * (Zk.y + Zm.y), oi = 0.5f * (Zm.x - Zk.x);
            float sv, cv; sincospif((float)k * (1.0f / 1024.0f), &sv, &cv);
            out[k] = make_float2(SC * (er + cv * orr + sv * oi),
                                 SC * (ei + cv * oi - sv * orr));
        }
    }
}

// ---------- K2: block MLP via mma.sync bf16 ----------
// grid (9 ktiles of 128, 64 = n*8+c, B), 256 threads = 8 warps (M16 stripes), occ 2.
// smem: Xa[128][66] u32 (A pairs, word = kk>>1) | W1s | W2s | bias1[128] | bias2[128]
// Oa/Ob (bf16 out staging) overlay Xa after the mid-barrier.
__global__ __launch_bounds__(256, 2) void k_mlp(const float* __restrict__ b1g,
                                                const float* __restrict__ b2g) {
    uint32_t* Xa  = (uint32_t*)smbase;       // 8448 words
    uint32_t* W1s = Xa + 8448;
    uint32_t* W2s = W1s + 8448;
    float* bias1 = (float*)(W2s + 8448);
    float* bias2 = bias1 + 128;
    uint16_t* Oa = (uint16_t*)Xa;            // [128][66] bf16 (real outs)
    uint16_t* Ob = Oa + 8448;                // [128][66] bf16 (imag outs)

    const int tid = threadIdx.x;
    const int w = tid >> 5, l = tid & 31;
    const int g = l >> 2, c = l & 3;
    const int k0 = blockIdx.x * 128;
    const int n = blockIdx.y >> 3, cch = blockIdx.y & 7;
    const int b = blockIdx.z;

    // weights (packed images) -> smem, padded rows of 66 words
    {
        const uint32_t* s1 = g_Wimg + (size_t)n * 8192;
        const uint32_t* s2 = g_Wimg + (size_t)(8 + n) * 8192;
        for (int idx = tid; idx < 8192; idx += 256) {
            int r = idx >> 6, col = idx & 63;
            W1s[r * 66 + col] = s1[idx];
            W2s[r * 66 + col] = s2[idx];
        }
    }
    if (tid < 128) {
        bias1[tid] = (tid < 64) ? b1g[n * 64 + tid] : b1g[512 + n * 64 + (tid - 64)];
        bias2[tid] = (tid < 64) ? b2g[n * 64 + tid] : b2g[512 + n * 64 + (tid - 64)];
    }
    // X tile fill: lane = k row (coalesced along k), pack i-pairs
    const size_t jstride = (size_t)8 * KPAD;
    const size_t rbase = ((size_t)b * PCN + (size_t)(n * 64) * 8 + cch) * KPAD + k0;
    {
        const int m = tid & 127, ih = tid >> 7;
        const bool valid = (k0 + m <= 1024);
        const float2* src = g_Y + rbase + m;
        for (int j = 2 * ih; j < 64; j += 4) {
            float2 va = make_float2(0.f, 0.f), vb = make_float2(0.f, 0.f);
            if (valid) { va = src[(size_t)j * jstride]; vb = src[(size_t)(j + 1) * jstride]; }
            Xa[m * 66 + (j >> 1)]      = pkbf(va.x, vb.x);
            Xa[m * 66 + 32 + (j >> 1)] = pkbf(va.y, vb.y);
        }
    }
    __syncthreads();

    const int mg = w * 16 + g;
    uint32_t hp0[16], hp1[16];

    // ---- layer 1 (two N-halves of 8 tiles to bound register use)
    #pragma unroll
    for (int h = 0; h < 2; ++h) {
        float acc[8][4];
        #pragma unroll
        for (int t = 0; t < 8; ++t)
            acc[t][0] = acc[t][1] = acc[t][2] = acc[t][3] = 0.f;
        #pragma unroll
        for (int s = 0; s < 8; ++s) {
            const int ko = 8 * s + c;
            uint32_t a0 = Xa[mg * 66 + ko];
            uint32_t a1 = Xa[(mg + 8) * 66 + ko];
            uint32_t a2 = Xa[mg * 66 + ko + 4];
            uint32_t a3 = Xa[(mg + 8) * 66 + ko + 4];
            #pragma unroll
            for (int t = 0; t < 8; ++t) {
                const int nr = (h * 8 + t) * 8 + g;
                mma16816(acc[t], a0, a1, a2, a3,
                         W1s[nr * 66 + ko], W1s[nr * 66 + ko + 4]);
            }
        }
        #pragma unroll
        for (int t = 0; t < 8; ++t) {
            const int nt = h * 8 + t;
            float2 bv = *(float2*)(bias1 + nt * 8 + 2 * c);
            hp0[nt] = pkbf(gelu_exact(acc[t][0] + bv.x), gelu_exact(acc[t][1] + bv.y));
            hp1[nt] = pkbf(gelu_exact(acc[t][2] + bv.x), gelu_exact(acc[t][3] + bv.y));
        }
    }
    __syncthreads();   // all warps done with Xa/W1s -> Oa/Ob overlay safe

    // ---- layer 2 (A-operand = hp in registers; C-frag layout == A-frag layout)
    #pragma unroll
    for (int h = 0; h < 2; ++h) {
        float acc[8][4];
        #pragma unroll
        for (int t = 0; t < 8; ++t)
            acc[t][0] = acc[t][1] = acc[t][2] = acc[t][3] = 0.f;
        #pragma unroll
        for (int s = 0; s < 8; ++s) {
            const int ko = 8 * s + c;
            uint32_t a0 = hp0[2 * s], a1 = hp1[2 * s];
            uint32_t a2 = hp0[2 * s + 1], a3 = hp1[2 * s + 1];
            #pragma unroll
            for (int t = 0; t < 8; ++t) {
                const int nr = (h * 8 + t) * 8 + g;
                mma16816(acc[t], a0, a1, a2, a3,
                         W2s[nr * 66 + ko], W2s[nr * 66 + ko + 4]);
            }
        }
        uint16_t* O = h ? Ob : Oa;
        const float* bs = bias2 + h * 64;
        #pragma unroll
        for (int t = 0; t < 8; ++t) {
            const int j = t * 8 + 2 * c;
            *(__nv_bfloat16*)&O[mg * 66 + j]           = __float2bfloat16(acc[t][0] + bs[j]);
            *(__nv_bfloat16*)&O[mg * 66 + j + 1]       = __float2bfloat16(acc[t][1] + bs[j + 1]);
            *(__nv_bfloat16*)&O[(mg + 8) * 66 + j]     = __float2bfloat16(acc[t][2] + bs[j]);
            *(__nv_bfloat16*)&O[(mg + 8) * 66 + j + 1] = __float2bfloat16(acc[t][3] + bs[j + 1]);
        }
    }
    __syncthreads();

    // ---- coalesced store back to g_Y
    {
        const int m = tid & 127, jh = tid >> 7;
        if (k0 + m <= 1024) {
            float2* dst = g_Y + rbase + m;
            for (int j = jh; j < 64; j += 2) {
                float vr = __bfloat162float(*(__nv_bfloat16*)&Oa[m * 66 + j]);
                float vi = __bfloat162float(*(__nv_bfloat16*)&Ob[m * 66 + j]);
                dst[(size_t)j * jstride] = make_float2(vr, vi);
            }
        }
    }
}

// ---------- K3: inverse rfft + residual ----------
__global__ __launch_bounds__(256, 3) void k_inv(const float* __restrict__ x,
                                                float* __restrict__ out) {
    float2* sm = (float2*)smbase;
    float2* W = sm;
    float2* lines = sm + 1024;
    const int tid = threadIdx.x;
    const int u = tid >> 6, t = tid & 63;
    const int pc0 = blockIdx.x * 4;
    const int b = blockIdx.y;

    for (int j = tid; j < 1024; j += 256) {
        float sv, cv; sincospif((float)j * (1.0f / 512.0f), &sv, &cv);
        W[j] = make_float2(cv, -sv);
    }
    float2* ls = lines + u * 1026;
    {
        const float2* src = g_Y + ((size_t)(b * PCN + pc0 + u)) * KPAD;
        for (int k = t; k <= 1024; k += 64) ls[PHY(k)] = src[k];
    }
    __syncthreads();

    const float SCI = 0.04419417382415922f;
    for (int k = t; k <= 512; k += 64) {
        float2 Xk = ls[PHY(k)];
        float2 Xj = ls[PHY(1024 - k)];
        if (k == 0) { Xk.y = 0.f; Xj.y = 0.f; }
        float ex = 0.5f * (Xk.x + Xj.x), ey = 0.5f * (Xk.y - Xj.y);
        float dx = 0.5f * (Xk.x - Xj.x), dy = 0.5f * (Xk.y + Xj.y);
        float sv, cv; sincospif((float)k * (1.0f / 1024.0f), &sv, &cv);
        float ox = cv * dx - sv * dy;
        float oy = cv * dy + sv * dx;
        ls[PHY(k)] = make_float2(SCI * (ex - oy), SCI * (ey + ox));
        if (k > 0 && k < 512)
            ls[PHY(1024 - k)] = make_float2(SCI * (ex + oy), SCI * (ox - ey));
    }
    __syncthreads();

    fft1024_f(ls, W, t, true);

    {
        const float* s0 = (const float*)lines;
        const float* xb = x + (size_t)b * LL * PCN + pc0;
        float* ob = out + (size_t)b * LL * PCN + pc0;
        for (int l = tid; l < 2048; l += 256) {
            float4 xv = *(const float4*)(xb + (size_t)l * PCN);
            int fo = 2 * PHY(l >> 1) + (l & 1);
            float4 r;
            r.x = xv.x + s0[0 * 2052 + fo];
            r.y = xv.y + s0[1 * 2052 + fo];
            r.z = xv.z + s0[2 * 2052 + fo];
            r.w = xv.w + s0[3 * 2052 + fo];
            *(float4*)(ob + (size_t)l * PCN) = r;
        }
    }
}

extern "C" void kernel_launch(void* const* d_in, const int* in_sizes, int n_in,
                              void* d_out, int out_size) {
    const float* x  = (const float*)d_in[0];
    const float* w1 = (const float*)d_in[1];
    const float* b1 = (const float*)d_in[2];
    const float* w2 = (const float*)d_in[3];
    const float* b2 = (const float*)d_in[4];
    float* out = (float*)d_out;

    const size_t s1 = (size_t)(1024 + 4 * 1025) * sizeof(float2);   // 40,992 B
    const size_t s2 = (size_t)3 * 8448 * 4 + 1024;                  // 102,400 B
    const size_t s3 = (size_t)(1024 + 4 * 1026) * sizeof(float2);   // 41,024 B

    cudaFuncSetAttribute(k_fwd, cudaFuncAttributeMaxDynamicSharedMemorySize, (int)s1);
    cudaFuncSetAttribute(k_mlp, cudaFuncAttributeMaxDynamicSharedMemorySize, (int)s2);
    cudaFuncSetAttribute(k_inv, cudaFuncAttributeMaxDynamicSharedMemorySize, (int)s3);

    k_wprep<<<dim3(8, 2), 256>>>(w1, w2);
    k_fwd<<<dim3(PCN / 4, BB), 256, s1>>>(x);
    k_mlp<<<dim3(9, 64, BB), 256, s2>>>(b1, b2);
    k_inv<<<dim3(PCN / 4, BB), 256, s3>>>(x, out);
}

// round 8
// speedup vs baseline: 2.3518x; 1.0787x over previous
#include <cuda_runtime.h>
#include <cuda_bf16.h>
#include <math.h>
#include <cstdint>

// Problem constants
#define BB   4
#define LL   2048
#define LF   1025
#define PP   512
#define CC   8
#define PCN  4096
#define NBL  8
#define BSZ  64
#define KPAD 1032
#define PHY(k) ((k) ^ (((k) >> 4) & 15))

typedef unsigned long long u64;

// 67.6 MB frequency scratch: [b][pc][k] bf16x2 (re low, im high)
__device__ uint32_t g_Y[(size_t)BB * PCN * KPAD];
// packed weight images: [layer][n][o=128][kk-pair word=64] bf16x2
__device__ uint32_t g_Wimg[2 * 8 * 8192];
// twiddle tables
__device__ float2 g_W1024[1024];   // e^{-2pi i j/1024}
__device__ float2 g_Whalf[1025];   // (cos(pi k/1024), sin(pi k/1024))

extern __shared__ unsigned char smbase[];

// ---------- helpers ----------
__device__ __forceinline__ float gelu_exact(float v) {
    return 0.5f * v * (1.0f + erff(v * 0.7071067811865475f));
}
__device__ __forceinline__ float2 cmulf(float2 x, float2 w) {
    return make_float2(x.x * w.x - x.y * w.y, x.x * w.y + x.y * w.x);
}
__device__ __forceinline__ float2 ldwt(const float2* W, int e, bool inv) {
    float2 w = W[e]; if (inv) w.y = -w.y; return w;
}
__device__ __forceinline__ void bfly4(float2& a, float2& b, float2& c, float2& d,
                                      float2 w1, float2 w2, float2 w3, bool inv) {
    float2 B = cmulf(b, w1), C = cmulf(c, w2), D = cmulf(d, w3);
    float2 t0 = make_float2(a.x + C.x, a.y + C.y);
    float2 t1 = make_float2(a.x - C.x, a.y - C.y);
    float2 t2 = make_float2(B.x + D.x, B.y + D.y);
    float2 t3 = make_float2(B.x - D.x, B.y - D.y);
    a = make_float2(t0.x + t2.x, t0.y + t2.y);
    c = make_float2(t0.x - t2.x, t0.y - t2.y);
    if (!inv) { b = make_float2(t1.x + t3.y, t1.y - t3.x);
                d = make_float2(t1.x - t3.y, t1.y + t3.x); }
    else      { b = make_float2(t1.x - t3.y, t1.y + t3.x);
                d = make_float2(t1.x + t3.y, t1.y - t3.x); }
}
__device__ __forceinline__ void bfly4n(float2& a, float2& b, float2& c, float2& d, bool inv) {
    float2 t0 = make_float2(a.x + c.x, a.y + c.y);
    float2 t1 = make_float2(a.x - c.x, a.y - c.y);
    float2 t2 = make_float2(b.x + d.x, b.y + d.y);
    float2 t3 = make_float2(b.x - d.x, b.y - d.y);
    a = make_float2(t0.x + t2.x, t0.y + t2.y);
    c = make_float2(t0.x - t2.x, t0.y - t2.y);
    if (!inv) { b = make_float2(t1.x + t3.y, t1.y - t3.x);
                d = make_float2(t1.x - t3.y, t1.y + t3.x); }
    else      { b = make_float2(t1.x - t3.y, t1.y + t3.x);
                d = make_float2(t1.x + t3.y, t1.y - t3.x); }
}
__device__ __forceinline__ uint32_t pkbf(float a, float b) {
    __nv_bfloat162 h = __floats2bfloat162_rn(a, b);
    return *(uint32_t*)&h;
}
__device__ __forceinline__ float2 upbf(uint32_t w) {
    __nv_bfloat162 h = *(__nv_bfloat162*)&w;
    return __bfloat1622float2(h);
}
__device__ __forceinline__ void mma16816(float* d, uint32_t a0, uint32_t a1,
                                         uint32_t a2, uint32_t a3,
                                         uint32_t b0, uint32_t b1) {
    asm volatile("mma.sync.aligned.m16n8k16.row.col.f32.bf16.bf16.f32 "
                 "{%0,%1,%2,%3}, {%4,%5,%6,%7}, {%8,%9}, {%0,%1,%2,%3};"
                 : "+f"(d[0]), "+f"(d[1]), "+f"(d[2]), "+f"(d[3])
                 : "r"(a0), "r"(a1), "r"(a2), "r"(a3), "r"(b0), "r"(b1));
}

// In-smem 1024-point FFT: 3 passes, PHY bank swizzle. t = 0..63.
__device__ __forceinline__ void fft1024_f(float2* ls, const float2* W, int t, bool inv) {
    {
        const int i0 = t << 4;
        const int rt = ((t & 3) << 4) | (((t >> 2) & 3) << 2) | (t >> 4);
        float2 x[16];
        #pragma unroll
        for (int m = 0; m < 16; ++m)
            x[m] = ls[PHY(rt + ((m & 3) << 8) + ((m >> 2) << 6))];
        #pragma unroll
        for (int a = 0; a < 4; ++a)
            bfly4n(x[4 * a], x[4 * a + 1], x[4 * a + 2], x[4 * a + 3], inv);
        #pragma unroll
        for (int r = 1; r < 4; ++r) {
            int e2 = r << 6;
            bfly4(x[r], x[4 + r], x[8 + r], x[12 + r],
                  ldwt(W, e2, inv), ldwt(W, 2 * e2, inv), ldwt(W, 3 * e2, inv), inv);
        }
        bfly4n(x[0], x[4], x[8], x[12], inv);
        #pragma unroll
        for (int m = 0; m < 16; ++m) ls[PHY(i0 + m)] = x[m];
    }
    __syncthreads();
    {
        const int j = t & 15;
        const int i0 = ((t >> 4) << 8) + j;
        float2 x[16];
        #pragma unroll
        for (int m = 0; m < 16; ++m) x[m] = ls[PHY(i0 + (m << 4))];
        const int e1 = j << 4;
        {
            float2 w1 = ldwt(W, e1, inv), w2 = ldwt(W, 2 * e1, inv), w3 = ldwt(W, 3 * e1, inv);
            #pragma unroll
            for (int a = 0; a < 4; ++a)
                bfly4(x[4 * a], x[4 * a + 1], x[4 * a + 2], x[4 * a + 3], w1, w2, w3, inv);
        }
        #pragma unroll
        for (int r = 0; r < 4; ++r) {
            int e2 = (j << 2) + (r << 6);
            bfly4(x[r], x[4 + r], x[8 + r], x[12 + r],
                  ldwt(W, e2, inv), ldwt(W, 2 * e2, inv), ldwt(W, 3 * e2, inv), inv);
        }
        #pragma unroll
        for (int m = 0; m < 16; ++m) ls[PHY(i0 + (m << 4))] = x[m];
    }
    __syncthreads();
    #pragma unroll
    for (int it = 0; it < 4; ++it) {
        int j = t + (it << 6);
        float2 w1 = ldwt(W, j, inv), w2 = ldwt(W, 2 * j, inv), w3 = ldwt(W, 3 * j, inv);
        float2 a = ls[PHY(j)], b = ls[PHY(j + 256)], c = ls[PHY(j + 512)], d = ls[PHY(j + 768)];
        bfly4(a, b, c, d, w1, w2, w3, inv);
        ls[PHY(j)] = a; ls[PHY(j + 256)] = b; ls[PHY(j + 512)] = c; ls[PHY(j + 768)] = d;
    }
    __syncthreads();
}

// ---------- K_tw: build twiddle tables ----------
__global__ void k_tw() {
    for (int j = threadIdx.x; j < 1024; j += 256) {
        float sv, cv; sincospif((float)j * (1.0f / 512.0f), &sv, &cv);
        g_W1024[j] = make_float2(cv, -sv);
    }
    for (int k = threadIdx.x; k <= 1024; k += 256) {
        float sv, cv; sincospif((float)k * (1.0f / 1024.0f), &sv, &cv);
        g_Whalf[k] = make_float2(cv, sv);
    }
}

// ---------- K0: pack weight images ----------
__global__ void k_wprep(const float* __restrict__ w1g, const float* __restrict__ w2g) {
    const int n = blockIdx.x, l = blockIdx.y;
    const float* wg = l ? w2g : w1g;
    uint32_t* dst = g_Wimg + (size_t)(l * 8 + n) * 8192;
    for (int idx = threadIdx.x; idx < 8192; idx += 256) {
        int o = idx >> 6, wd = idx & 63;
        float v[2];
        #pragma unroll
        for (int q = 0; q < 2; ++q) {
            int kk = 2 * wd + q;
            if (o < 64)
                v[q] = (kk < 64) ? wg[n * 4096 + kk * 64 + o]
                                 : -wg[32768 + n * 4096 + (kk - 64) * 64 + o];
            else
                v[q] = (kk < 64) ? wg[32768 + n * 4096 + kk * 64 + (o - 64)]
                                 : wg[n * 4096 + (kk - 64) * 64 + (o - 64)];
        }
        dst[idx] = pkbf(v[0], v[1]);
    }
}

// ---------- K1: forward rfft ----------
__global__ __launch_bounds__(256, 3) void k_fwd(const float* __restrict__ x) {
    float2* sm = (float2*)smbase;
    float2* W = sm;
    float2* lines = sm + 1024;
    const int tid = threadIdx.x;
    const int u = tid >> 6, t = tid & 63;
    const int pc0 = blockIdx.x * 4;
    const int b = blockIdx.y;

    for (int j = tid; j < 1024; j += 256) W[j] = g_W1024[j];
    {
        const float* xb = x + (size_t)b * LL * PCN + pc0;
        for (int l = tid; l < 2048; l += 256) {
            float4 v = *(const float4*)(xb + (size_t)l * PCN);
            int fo = 2 * PHY(l >> 1) + (l & 1);
            float* s0 = (float*)lines;
            s0[0 * 2050 + fo] = v.x;
            s0[1 * 2050 + fo] = v.y;
            s0[2 * 2050 + fo] = v.z;
            s0[3 * 2050 + fo] = v.w;
        }
    }
    __syncthreads();

    float2* ls = lines + u * 1025;
    fft1024_f(ls, W, t, false);

    {   // rfft unpack + ortho scale, bf16 store (coalesced)
        uint32_t* out = g_Y + ((size_t)(b * PCN + pc0 + u)) * KPAD;
        const float SC = 0.02209708691207961f;
        for (int k = t; k <= 1024; k += 64) {
            float2 Zk = ls[PHY(k & 1023)];
            float2 Zm = ls[PHY((1024 - k) & 1023)];
            float er = 0.5f * (Zk.x + Zm.x), ei = 0.5f * (Zk.y - Zm.y);
            float orr = 0.5f * (Zk.y + Zm.y), oi = 0.5f * (Zm.x - Zk.x);
            float2 wv = g_Whalf[k];
            out[k] = pkbf(SC * (er + wv.x * orr + wv.y * oi),
                          SC * (ei + wv.x * oi - wv.y * orr));
        }
    }
}

// ---------- K2: block MLP via mma.sync bf16 ----------
__global__ __launch_bounds__(256, 2) void k_mlp(const float* __restrict__ b1g,
                                                const float* __restrict__ b2g) {
    uint32_t* Xa  = (uint32_t*)smbase;       // 8448 words
    uint32_t* W1s = Xa + 8448;
    uint32_t* W2s = W1s + 8448;
    float* bias1 = (float*)(W2s + 8448);
    float* bias2 = bias1 + 128;
    uint16_t* Oa = (uint16_t*)Xa;            // [128][66] bf16 bits (real outs)
    uint16_t* Ob = Oa + 8448;                // [128][66] bf16 bits (imag outs)

    const int tid = threadIdx.x;
    const int w = tid >> 5, l = tid & 31;
    const int g = l >> 2, c = l & 3;
    const int k0 = blockIdx.x * 128;
    const int n = blockIdx.y >> 3, cch = blockIdx.y & 7;
    const int b = blockIdx.z;

    {
        const uint32_t* s1 = g_Wimg + (size_t)n * 8192;
        const uint32_t* s2 = g_Wimg + (size_t)(8 + n) * 8192;
        for (int idx = tid; idx < 8192; idx += 256) {
            int r = idx >> 6, col = idx & 63;
            W1s[r * 66 + col] = s1[idx];
            W2s[r * 66 + col] = s2[idx];
        }
    }
    if (tid < 128) {
        bias1[tid] = (tid < 64) ? b1g[n * 64 + tid] : b1g[512 + n * 64 + (tid - 64)];
        bias2[tid] = (tid < 64) ? b2g[n * 64 + tid] : b2g[512 + n * 64 + (tid - 64)];
    }
    const size_t jstride = (size_t)8 * KPAD;
    const size_t rbase = ((size_t)b * PCN + (size_t)(n * 64) * 8 + cch) * KPAD + k0;
    {   // X fill: PRMT repack of bf16 pairs, coalesced along k
        const int m = tid & 127, ih = tid >> 7;
        const bool valid = (k0 + m <= 1024);
        const uint32_t* src = g_Y + rbase + m;
        for (int j = 2 * ih; j < 64; j += 4) {
            uint32_t w0 = 0, w1 = 0;
            if (valid) { w0 = src[(size_t)j * jstride]; w1 = src[(size_t)(j + 1) * jstride]; }
            uint32_t rp, ip;
            asm("prmt.b32 %0, %1, %2, 0x5410;" : "=r"(rp) : "r"(w0), "r"(w1));
            asm("prmt.b32 %0, %1, %2, 0x7632;" : "=r"(ip) : "r"(w0), "r"(w1));
            Xa[m * 66 + (j >> 1)]      = rp;
            Xa[m * 66 + 32 + (j >> 1)] = ip;
        }
    }
    __syncthreads();

    const int mg = w * 16 + g;
    uint32_t hp0[16], hp1[16];

    // ---- layer 1
    #pragma unroll
    for (int h = 0; h < 2; ++h) {
        float acc[8][4];
        #pragma unroll
        for (int t = 0; t < 8; ++t)
            acc[t][0] = acc[t][1] = acc[t][2] = acc[t][3] = 0.f;
        #pragma unroll
        for (int s = 0; s < 8; ++s) {
            const int ko = 8 * s + c;
            uint32_t a0 = Xa[mg * 66 + ko];
            uint32_t a1 = Xa[(mg + 8) * 66 + ko];
            uint32_t a2 = Xa[mg * 66 + ko + 4];
            uint32_t a3 = Xa[(mg + 8) * 66 + ko + 4];
            #pragma unroll
            for (int t = 0; t < 8; ++t) {
                const int nr = (h * 8 + t) * 8 + g;
                mma16816(acc[t], a0, a1, a2, a3,
                         W1s[nr * 66 + ko], W1s[nr * 66 + ko + 4]);
            }
        }
        #pragma unroll
        for (int t = 0; t < 8; ++t) {
            const int nt = h * 8 + t;
            float2 bv = *(float2*)(bias1 + nt * 8 + 2 * c);
            hp0[nt] = pkbf(gelu_exact(acc[t][0] + bv.x), gelu_exact(acc[t][1] + bv.y));
            hp1[nt] = pkbf(gelu_exact(acc[t][2] + bv.x), gelu_exact(acc[t][3] + bv.y));
        }
    }
    __syncthreads();

    // ---- layer 2 (A-operand in registers)
    #pragma unroll
    for (int h = 0; h < 2; ++h) {
        float acc[8][4];
        #pragma unroll
        for (int t = 0; t < 8; ++t)
            acc[t][0] = acc[t][1] = acc[t][2] = acc[t][3] = 0.f;
        #pragma unroll
        for (int s = 0; s < 8; ++s) {
            const int ko = 8 * s + c;
            uint32_t a0 = hp0[2 * s], a1 = hp1[2 * s];
            uint32_t a2 = hp0[2 * s + 1], a3 = hp1[2 * s + 1];
            #pragma unroll
            for (int t = 0; t < 8; ++t) {
                const int nr = (h * 8 + t) * 8 + g;
                mma16816(acc[t], a0, a1, a2, a3,
                         W2s[nr * 66 + ko], W2s[nr * 66 + ko + 4]);
            }
        }
        uint16_t* O = h ? Ob : Oa;
        const float* bs = bias2 + h * 64;
        #pragma unroll
        for (int t = 0; t < 8; ++t) {
            const int j = t * 8 + 2 * c;
            __nv_bfloat16 h0 = __float2bfloat16(acc[t][0] + bs[j]);
            __nv_bfloat16 h1 = __float2bfloat16(acc[t][1] + bs[j + 1]);
            __nv_bfloat16 h2 = __float2bfloat16(acc[t][2] + bs[j]);
            __nv_bfloat16 h3 = __float2bfloat16(acc[t][3] + bs[j + 1]);
            O[mg * 66 + j]           = *(uint16_t*)&h0;
            O[mg * 66 + j + 1]       = *(uint16_t*)&h1;
            O[(mg + 8) * 66 + j]     = *(uint16_t*)&h2;
            O[(mg + 8) * 66 + j + 1] = *(uint16_t*)&h3;
        }
    }
    __syncthreads();

    {   // coalesced bf16x2 store
        const int m = tid & 127, jh = tid >> 7;
        if (k0 + m <= 1024) {
            uint32_t* dst = g_Y + rbase + m;
            for (int j = jh; j < 64; j += 2)
                dst[(size_t)j * jstride] =
                    (uint32_t)Oa[m * 66 + j] | ((uint32_t)Ob[m * 66 + j] << 16);
        }
    }
}

// ---------- K3: inverse rfft + residual (pack fused into load) ----------
__global__ __launch_bounds__(256, 3) void k_inv(const float* __restrict__ x,
                                                float* __restrict__ out) {
    float2* sm = (float2*)smbase;
    float2* W = sm;
    float2* lines = sm + 1024;
    const int tid = threadIdx.x;
    const int u = tid >> 6, t = tid & 63;
    const int pc0 = blockIdx.x * 4;
    const int b = blockIdx.y;

    for (int j = tid; j < 1024; j += 256) W[j] = g_W1024[j];
    float2* ls = lines + u * 1026;
    {   // load + hermitian pack in one pass (DC/Nyquist imag dropped)
        const uint32_t* src = g_Y + ((size_t)(b * PCN + pc0 + u)) * KPAD;
        const float SCI = 0.04419417382415922f;  // 2/sqrt(2048)
        for (int k = t; k <= 512; k += 64) {
            float2 Xk = upbf(src[k]);
            float2 Xj = upbf(src[1024 - k]);
            if (k == 0) { Xk.y = 0.f; Xj.y = 0.f; }
            float ex = 0.5f * (Xk.x + Xj.x), ey = 0.5f * (Xk.y - Xj.y);
            float dx = 0.5f * (Xk.x - Xj.x), dy = 0.5f * (Xk.y + Xj.y);
            float2 wv = g_Whalf[k];
            float ox = wv.x * dx - wv.y * dy;
            float oy = wv.x * dy + wv.y * dx;
            ls[PHY(k)] = make_float2(SCI * (ex - oy), SCI * (ey + ox));
            if (k > 0 && k < 512)
                ls[PHY(1024 - k)] = make_float2(SCI * (ex + oy), SCI * (ox - ey));
        }
    }
    __syncthreads();

    fft1024_f(ls, W, t, true);

    {
        const float* s0 = (const float*)lines;
        const float* xb = x + (size_t)b * LL * PCN + pc0;
        float* ob = out + (size_t)b * LL * PCN + pc0;
        for (int l = tid; l < 2048; l += 256) {
            float4 xv = *(const float4*)(xb + (size_t)l * PCN);
            int fo = 2 * PHY(l >> 1) + (l & 1);
            float4 r;
            r.x = xv.x + s0[0 * 2052 + fo];
            r.y = xv.y + s0[1 * 2052 + fo];
            r.z = xv.z + s0[2 * 2052 + fo];
            r.w = xv.w + s0[3 * 2052 + fo];
            *(float4*)(ob + (size_t)l * PCN) = r;
        }
    }
}

extern "C" void kernel_launch(void* const* d_in, const int* in_sizes, int n_in,
                              void* d_out, int out_size) {
    const float* x  = (const float*)d_in[0];
    const float* w1 = (const float*)d_in[1];
    const float* b1 = (const float*)d_in[2];
    const float* w2 = (const float*)d_in[3];
    const float* b2 = (const float*)d_in[4];
    float* out = (float*)d_out;

    const size_t s1 = (size_t)(1024 + 4 * 1025) * sizeof(float2);   // 40,992 B
    const size_t s2 = (size_t)3 * 8448 * 4 + 1024;                  // 102,400 B
    const size_t s3 = (size_t)(1024 + 4 * 1026) * sizeof(float2);   // 41,024 B

    cudaFuncSetAttribute(k_fwd, cudaFuncAttributeMaxDynamicSharedMemorySize, (int)s1);
    cudaFuncSetAttribute(k_mlp, cudaFuncAttributeMaxDynamicSharedMemorySize, (int)s2);
    cudaFuncSetAttribute(k_inv, cudaFuncAttributeMaxDynamicSharedMemorySize, (int)s3);

    k_tw<<<1, 256>>>();
    k_wprep<<<dim3(8, 2), 256>>>(w1, w2);
    k_fwd<<<dim3(PCN / 4, BB), 256, s1>>>(x);
    k_mlp<<<dim3(9, 64, BB), 256, s2>>>(b1, b2);
    k_inv<<<dim3(PCN / 4, BB), 256, s3>>>(x, out);
}